// round 5
// baseline (speedup 1.0000x reference)
#include <cuda_runtime.h>
#include <cuda_bf16.h>

// Problem constants (from reference)
#define V_SZ     32000
#define D_SZ     5120
#define T_SZ     32
#define B_SZ     4
#define S_SZ     2048
#define VIS_DIM  768
#define N_SHARED (V_SZ + 2)            // 32002
#define NTOK     (B_SZ * S_SZ)         // 8192
#define NROWS    (B_SZ * T_SZ)         // 128 vision rows

#define THREADS  256
#define VCHUNK   256                   // cols per vision chunk block
#define NVCHUNK  (D_SZ / VCHUNK)       // 20
#define TPB      8                     // tokens per gather block
#define NF4      (D_SZ / 4)            // 1280 float4 per row

// Scratch (device globals — no allocation)
__device__ float g_vx[(size_t)NROWS * D_SZ];   // [B*T, D] = 2.6 MB
__device__ int   g_used[NROWS];

// ---------------------------------------------------------------------------
// K0: mark referenced vision rows. 1 block, vectorized int4 loads (MLP=2).
// ---------------------------------------------------------------------------
__global__ __launch_bounds__(1024)
void mark_kernel(const int4* __restrict__ text4)   // 2048 int4 = 8192 ids
{
    __shared__ int s_used[NROWS];
    const int tid = threadIdx.x;
    if (tid < NROWS) s_used[tid] = 0;
    __syncthreads();

    int4 v0 = __ldg(&text4[tid]);          // tokens 4*tid   .. 4*tid+3
    int4 v1 = __ldg(&text4[tid + 1024]);   // tokens 4096+.. (second half)

    int b0 = (4 * tid) / S_SZ;             // all 4 ids in v0 share this b
    int b1 = (4 * (tid + 1024)) / S_SZ;

    #pragma unroll
    for (int k = 0; k < 4; k++) {
        int id0 = (k == 0) ? v0.x : (k == 1) ? v0.y : (k == 2) ? v0.z : v0.w;
        int id1 = (k == 0) ? v1.x : (k == 1) ? v1.y : (k == 2) ? v1.z : v1.w;
        if (id0 >= N_SHARED) {
            int tv = id0 - N_SHARED; if (tv > T_SZ - 1) tv = T_SZ - 1;
            s_used[b0 * T_SZ + tv] = 1;
        }
        if (id1 >= N_SHARED) {
            int tv = id1 - N_SHARED; if (tv > T_SZ - 1) tv = T_SZ - 1;
            s_used[b1 * T_SZ + tv] = 1;
        }
    }
    __syncthreads();
    if (tid < NROWS) g_used[tid] = s_used[tid];
}

// ---------------------------------------------------------------------------
// K1: vx[row] = vis[row] @ fc_w + fc_b for marked rows only.
// grid (128 rows, 20 chunks) x 256 threads; each thread -> 1 output col.
// ---------------------------------------------------------------------------
__global__ __launch_bounds__(THREADS)
void vx_kernel(const float* __restrict__ vis,     // [B*T, VIS_DIM]
               const float* __restrict__ fc_w,    // [VIS_DIM, D]
               const float* __restrict__ fc_b)    // [D]
{
    const int row = blockIdx.x;
    if (!g_used[row]) return;

    __shared__ float s_vis[VIS_DIM];
    const int tid = threadIdx.x;

    const float* vrow = vis + (size_t)row * VIS_DIM;
    for (int i = tid; i < VIS_DIM; i += THREADS) s_vis[i] = vrow[i];
    __syncthreads();

    const int col = blockIdx.y * VCHUNK + tid;
    float acc = __ldg(&fc_b[col]);
    const float* w = fc_w + col;

    #pragma unroll 8
    for (int k = 0; k < VIS_DIM; k++)
        acc = fmaf(s_vis[k], __ldg(&w[(size_t)k * D_SZ]), acc);

    g_vx[(size_t)row * D_SZ + col] = acc;
}

// ---------------------------------------------------------------------------
// K2: row gather, 8 tokens per block, register double-buffered copy.
// ---------------------------------------------------------------------------
__device__ __forceinline__ const float4*
src_ptr(int id, int tok, const float* weight, const float* fig)
{
    const float* s;
    if (id < V_SZ) {
        s = weight + (size_t)id * D_SZ;
    } else if (id < N_SHARED) {
        s = fig + (size_t)(id - V_SZ) * D_SZ;
    } else {
        int tv = id - N_SHARED;
        if (tv > T_SZ - 1) tv = T_SZ - 1;
        int b = tok / S_SZ;
        s = g_vx + ((size_t)(b * T_SZ + tv)) * D_SZ;
    }
    return (const float4*)s;
}

__global__ __launch_bounds__(THREADS)
void gather_kernel(const int*   __restrict__ text,
                   const float* __restrict__ weight,
                   const float* __restrict__ fig,
                   float*       __restrict__ out)
{
    const int base = blockIdx.x * TPB;
    const int tid  = threadIdx.x;

    // all 8 token ids up front (two int4 loads, text is 32B-aligned at base)
    int4 ia = __ldg((const int4*)(text + base));
    int4 ib = __ldg((const int4*)(text + base + 4));
    int ids[TPB] = { ia.x, ia.y, ia.z, ia.w, ib.x, ib.y, ib.z, ib.w };

    float4 cur[5], nxt[5];

    // prologue: load token 0
    {
        const float4* s = src_ptr(ids[0], base, weight, fig);
        #pragma unroll
        for (int k = 0; k < 5; k++) cur[k] = __ldg(s + tid + k * THREADS);
    }

    #pragma unroll
    for (int t = 0; t < TPB; t++) {
        // issue next token's loads before this token's stores
        if (t + 1 < TPB) {
            const float4* s = src_ptr(ids[t + 1], base + t + 1, weight, fig);
            #pragma unroll
            for (int k = 0; k < 5; k++) nxt[k] = __ldg(s + tid + k * THREADS);
        }
        float4* d = (float4*)(out + (size_t)(base + t) * D_SZ);
        #pragma unroll
        for (int k = 0; k < 5; k++) __stcs(d + tid + k * THREADS, cur[k]);
        #pragma unroll
        for (int k = 0; k < 5; k++) cur[k] = nxt[k];
    }
}

extern "C" void kernel_launch(void* const* d_in, const int* in_sizes, int n_in,
                              void* d_out, int out_size)
{
    const int*   text   = (const int*)  d_in[0];  // [B,S] int32
    const float* vis    = (const float*)d_in[1];  // [B,T,VIS_DIM]
    const float* weight = (const float*)d_in[2];  // [V,D]
    const float* fig    = (const float*)d_in[3];  // [2,D]
    const float* fc_w   = (const float*)d_in[4];  // [VIS_DIM,D]
    const float* fc_b   = (const float*)d_in[5];  // [D]
    float*       out    = (float*)d_out;

    mark_kernel<<<1, 1024>>>((const int4*)text);
    vx_kernel<<<dim3(NROWS, NVCHUNK), THREADS>>>(vis, fc_w, fc_b);
    gather_kernel<<<NTOK / TPB, THREADS>>>(text, weight, fig, out);
}